// round 1
// baseline (speedup 1.0000x reference)
#include <cuda_runtime.h>
#include <cuda_bf16.h>
#include <math.h>

// ---------------- problem constants ----------------
#define NN   50000
#define EE   1600000
#define GG   64
#define HIDD 128

// ---------------- device scratch (no allocation allowed) ----------------
__device__ float g_h0[(size_t)NN * HIDD];
__device__ float g_h1[(size_t)NN * HIDD];
__device__ float g_hf[(size_t)NN * HIDD];
__device__ float g_dinv[NN];
__device__ int   g_deg[NN];
__device__ int   g_off[NN + 1];
__device__ int   g_cur[NN];
__device__ int   g_srcv[EE + NN];
__device__ float g_wte[64 * 16 * 128];        // embed weights transposed [K=1024][128]
__device__ float g_wtm[3 * 128 * 16 * 128];   // mp weights transposed    [K=2048][128] x3
__device__ float g_wtr[128 * 16 * 32];        // readout transposed       [K=2048][32]
__device__ float g_sums[GG * HIDD];
__device__ float g_cnts[GG];

// ---------------- f32x2 helpers (FFMA2 = 2x fp32 rate on sm_103a) ----------------
__device__ __forceinline__ unsigned long long pk(float x, float y) {
    unsigned long long r;
    asm("mov.b64 %0, {%1, %2};" : "=l"(r) : "f"(x), "f"(y));
    return r;
}
__device__ __forceinline__ unsigned long long f2fma(unsigned long long a,
                                                    unsigned long long b,
                                                    unsigned long long c) {
    unsigned long long d;
    asm("fma.rn.f32x2 %0, %1, %2, %3;" : "=l"(d) : "l"(a), "l"(b), "l"(c));
    return d;
}
__device__ __forceinline__ float2 upk(unsigned long long v) {
    float2 f;
    asm("mov.b64 {%0, %1}, %2;" : "=f"(f.x), "=f"(f.y) : "l"(v));
    return f;
}

// ---------------- small utility kernels ----------------
__global__ void zero_i32(int* __restrict__ p, int n) {
    int i = blockIdx.x * blockDim.x + threadIdx.x;
    if (i < n) p[i] = 0;
}
__global__ void zero_f32(float* __restrict__ p, int n) {
    int i = blockIdx.x * blockDim.x + threadIdx.x;
    if (i < n) p[i] = 0.0f;
}
__global__ void count_deg(const int* __restrict__ ecol, int* __restrict__ deg) {
    int e = blockIdx.x * blockDim.x + threadIdx.x;
    if (e < EE) atomicAdd(&deg[ecol[e]], 1);
}
__global__ void compute_dinv(const int* __restrict__ deg, float* __restrict__ dinv) {
    int i = blockIdx.x * blockDim.x + threadIdx.x;
    if (i < NN) dinv[i] = rsqrtf((float)(deg[i] + 1));  // +1 self loop; always > 0
}

// exclusive scan of (deg[i]+1) into off[], copy into cur[]; single block of 1024
__global__ void scan_offsets(const int* __restrict__ deg, int* __restrict__ off,
                             int* __restrict__ cur) {
    __shared__ int sh[1024];
    const int t = threadIdx.x;
    const int CH = (NN + 1023) / 1024;
    int base = t * CH;
    int local = 0;
    for (int j = 0; j < CH; j++) {
        int idx = base + j;
        if (idx < NN) local += deg[idx] + 1;
    }
    sh[t] = local;
    __syncthreads();
    for (int d = 1; d < 1024; d <<= 1) {
        int v = (t >= d) ? sh[t - d] : 0;
        __syncthreads();
        sh[t] += v;
        __syncthreads();
    }
    int run = (t == 0) ? 0 : sh[t - 1];
    for (int j = 0; j < CH; j++) {
        int idx = base + j;
        if (idx < NN) {
            off[idx] = run;
            cur[idx] = run;
            run += deg[idx] + 1;
        }
    }
    if (t == 1023) off[NN] = run;
}

__global__ void fill_csr(const int* __restrict__ erow, const int* __restrict__ ecol,
                         int* __restrict__ cur, int* __restrict__ srcv) {
    int e = blockIdx.x * blockDim.x + threadIdx.x;
    if (e >= EE + NN) return;
    int r, c;
    if (e < EE) { r = erow[e]; c = ecol[e]; }
    else        { r = c = e - EE; }             // self loops
    int p = atomicAdd(&cur[c], 1);
    srcv[p] = r;
}

// W[2][out][in][8] -> Wt[k][out], k = i*16 + t*8 + h
__global__ void transpose_w(const float* __restrict__ W, float* __restrict__ Wt,
                            int in_dim, int out_dim) {
    int idx = blockIdx.x * blockDim.x + threadIdx.x;
    int total = in_dim * 16 * out_dim;
    if (idx >= total) return;
    int o = idx % out_dim;
    int k = idx / out_dim;
    int h = k & 7;
    int t = (k >> 3) & 1;
    int i = k >> 4;
    Wt[idx] = W[(((size_t)t * out_dim + o) * in_dim + i) * 8 + h];
}

// ---------------- KAN GEMM: out[row][0..127] = phi(in[row]) @ Wt ----------------
// phi expands each input feature into cos(kx),sin(kx), k=1..8 (16 values).
// in_scale (nullable) scales input rows; out_scale (nullable) scales output rows.
__global__ __launch_bounds__(256, 3)
void kan_gemm(const float* __restrict__ in, int in_dim, int n_rows,
              const float* __restrict__ Wt,
              const float* __restrict__ in_scale,
              const float* __restrict__ out_scale,
              float* __restrict__ out) {
    __shared__ float As[64][64];    // [k_local][row]  16KB
    __shared__ float Bs[64][128];   // [k_local][out]  32KB

    const int tid  = threadIdx.x;
    const int row0 = blockIdx.x * 64;
    const int tx = tid & 15;        // 8 output cols each
    const int ty = tid >> 4;        // 4 rows each

    unsigned long long acc[4][4];
    const unsigned long long z = pk(0.0f, 0.0f);
#pragma unroll
    for (int r = 0; r < 4; r++)
#pragma unroll
        for (int c = 0; c < 4; c++) acc[r][c] = z;

    const int il = tid >> 6;        // feature-within-chunk 0..3
    const int rr = tid & 63;        // row-within-tile
    const int grow = row0 + rr;
    const bool rvalid = grow < n_rows;
    const float isc = (rvalid && in_scale) ? in_scale[grow] : 1.0f;

    for (int i0 = 0; i0 < in_dim; i0 += 4) {
        __syncthreads();
        // --- expansion into As (1 sincos + Chebyshev recurrence per element) ---
        {
            float x = rvalid ? in[(size_t)grow * in_dim + i0 + il] * isc : 0.0f;
            float s1, c1;
            sincosf(x, &s1, &c1);
            const float twoc = 2.0f * c1;
            float cp = 1.0f, sp = 0.0f, cc = c1, ss = s1;
#pragma unroll
            for (int h = 0; h < 8; h++) {
                As[il * 16 + h][rr]     = cc;   // cos((h+1)x)
                As[il * 16 + 8 + h][rr] = ss;   // sin((h+1)x)
                float cn = twoc * cc - cp;
                float sn = twoc * ss - sp;
                cp = cc; sp = ss; cc = cn; ss = sn;
            }
        }
        // --- B tile: 64x128 floats, coalesced float4 copies ---
        {
            const float4* s4 = reinterpret_cast<const float4*>(Wt + (size_t)i0 * 16 * 128);
            float4* d4 = reinterpret_cast<float4*>(&Bs[0][0]);
#pragma unroll
            for (int j = 0; j < 8; j++) d4[j * 256 + tid] = s4[j * 256 + tid];
        }
        __syncthreads();
        // --- inner product, FFMA2 ---
#pragma unroll 8
        for (int kk = 0; kk < 64; kk++) {
            const float4 a4 = *reinterpret_cast<const float4*>(&As[kk][ty * 4]);
            const ulonglong2 b01 = *reinterpret_cast<const ulonglong2*>(&Bs[kk][tx * 8]);
            const ulonglong2 b23 = *reinterpret_cast<const ulonglong2*>(&Bs[kk][tx * 8 + 4]);
            unsigned long long pa;
#define ROW_FMA(R, AV)                                                   \
            pa = pk(AV, AV);                                             \
            acc[R][0] = f2fma(pa, b01.x, acc[R][0]);                     \
            acc[R][1] = f2fma(pa, b01.y, acc[R][1]);                     \
            acc[R][2] = f2fma(pa, b23.x, acc[R][2]);                     \
            acc[R][3] = f2fma(pa, b23.y, acc[R][3]);
            ROW_FMA(0, a4.x)
            ROW_FMA(1, a4.y)
            ROW_FMA(2, a4.z)
            ROW_FMA(3, a4.w)
#undef ROW_FMA
        }
    }
    // --- epilogue ---
#pragma unroll
    for (int r = 0; r < 4; r++) {
        int row = row0 + ty * 4 + r;
        if (row < n_rows) {
            float sc = out_scale ? out_scale[row] : 1.0f;
            float2 p0 = upk(acc[r][0]), p1 = upk(acc[r][1]);
            float2 p2 = upk(acc[r][2]), p3 = upk(acc[r][3]);
            float4* po = reinterpret_cast<float4*>(out + (size_t)row * 128 + tx * 8);
            po[0] = make_float4(p0.x * sc, p0.y * sc, p1.x * sc, p1.y * sc);
            po[1] = make_float4(p2.x * sc, p2.y * sc, p3.x * sc, p3.y * sc);
        }
    }
}

// ---------------- CSR aggregation: out[c] = sum over incoming edges hf[src] ----------------
__global__ void aggregate(const float* __restrict__ hf,
                          const int* __restrict__ off, const int* __restrict__ srcv,
                          float* __restrict__ out) {
    int warp = (blockIdx.x * blockDim.x + threadIdx.x) >> 5;
    int lane = threadIdx.x & 31;
    if (warp >= NN) return;
    int e  = off[warp];
    int e1 = off[warp + 1];
    float4 a0 = make_float4(0.f, 0.f, 0.f, 0.f);
    float4 a1 = make_float4(0.f, 0.f, 0.f, 0.f);
    for (; e + 1 < e1; e += 2) {
        int r0 = __ldg(&srcv[e]);
        int r1 = __ldg(&srcv[e + 1]);
        float4 v0 = *reinterpret_cast<const float4*>(hf + (size_t)r0 * 128 + lane * 4);
        float4 v1 = *reinterpret_cast<const float4*>(hf + (size_t)r1 * 128 + lane * 4);
        a0.x += v0.x; a0.y += v0.y; a0.z += v0.z; a0.w += v0.w;
        a1.x += v1.x; a1.y += v1.y; a1.z += v1.z; a1.w += v1.w;
    }
    if (e < e1) {
        int r0 = __ldg(&srcv[e]);
        float4 v0 = *reinterpret_cast<const float4*>(hf + (size_t)r0 * 128 + lane * 4);
        a0.x += v0.x; a0.y += v0.y; a0.z += v0.z; a0.w += v0.w;
    }
    a0.x += a1.x; a0.y += a1.y; a0.z += a1.z; a0.w += a1.w;
    *reinterpret_cast<float4*>(out + (size_t)warp * 128 + lane * 4) = a0;
}

// ---------------- pooling: sums[g] += dinv[n]*h[n], cnts[g] += 1 ----------------
__global__ void pool_kernel(const float* __restrict__ h, const int* __restrict__ batch,
                            const float* __restrict__ dinv,
                            float* __restrict__ sums, float* __restrict__ cnts) {
    const int PER = 25;                       // 2000 warps cover 50000 nodes
    int warp = (blockIdx.x * blockDim.x + threadIdx.x) >> 5;
    int lane = threadIdx.x & 31;
    int n0 = warp * PER;
    if (n0 >= NN) return;
    int n1 = n0 + PER;
    if (n1 > NN) n1 = NN;
    float4 acc = make_float4(0.f, 0.f, 0.f, 0.f);
    float cnt = 0.f;
    int cg = batch[n0];
    for (int n = n0; n < n1; n++) {
        int g = batch[n];
        if (g != cg) {
            float* p = sums + (size_t)cg * 128 + lane * 4;
            atomicAdd(p + 0, acc.x); atomicAdd(p + 1, acc.y);
            atomicAdd(p + 2, acc.z); atomicAdd(p + 3, acc.w);
            if (lane == 0) atomicAdd(&cnts[cg], cnt);
            acc = make_float4(0.f, 0.f, 0.f, 0.f);
            cnt = 0.f; cg = g;
        }
        float w = dinv[n];
        float4 v = *reinterpret_cast<const float4*>(h + (size_t)n * 128 + lane * 4);
        acc.x += w * v.x; acc.y += w * v.y; acc.z += w * v.z; acc.w += w * v.w;
        cnt += 1.f;
    }
    float* p = sums + (size_t)cg * 128 + lane * 4;
    atomicAdd(p + 0, acc.x); atomicAdd(p + 1, acc.y);
    atomicAdd(p + 2, acc.z); atomicAdd(p + 3, acc.w);
    if (lane == 0) atomicAdd(&cnts[cg], cnt);
}

// ---------------- readout: y = sums/max(cnt,1); out = kan(y, W_read) ----------------
__global__ void readout_kernel(const float* __restrict__ sums, const float* __restrict__ cnts,
                               const float* __restrict__ Wt /*[2048][32]*/,
                               float* __restrict__ out) {
    __shared__ float phi[2048];
    __shared__ float red[4][32];
    const int g = blockIdx.x;
    const int tid = threadIdx.x;          // 128 threads
    float cnt = fmaxf(cnts[g], 1.0f);
    float x = sums[(size_t)g * 128 + tid] / cnt;
    float s1, c1;
    sincosf(x, &s1, &c1);
    const float twoc = 2.0f * c1;
    float cp = 1.0f, sp = 0.0f, cc = c1, ss = s1;
#pragma unroll
    for (int h = 0; h < 8; h++) {
        phi[tid * 16 + h]     = cc;
        phi[tid * 16 + 8 + h] = ss;
        float cn = twoc * cc - cp;
        float sn = twoc * ss - sp;
        cp = cc; sp = ss; cc = cn; ss = sn;
    }
    __syncthreads();
    const int o = tid & 31;
    const int part = tid >> 5;            // 4 K-slices of 512
    float acc = 0.f;
    int k0 = part * 512;
#pragma unroll 8
    for (int k = k0; k < k0 + 512; k++) acc += phi[k] * Wt[k * 32 + o];
    red[part][o] = acc;
    __syncthreads();
    if (tid < 32)
        out[(size_t)g * 32 + tid] = red[0][tid] + red[1][tid] + red[2][tid] + red[3][tid];
}

// ---------------- launch ----------------
extern "C" void kernel_launch(void* const* d_in, const int* in_sizes, int n_in,
                              void* d_out, int out_size) {
    const float* features = (const float*)d_in[0];   // [N,64]
    const int*   edges    = (const int*)d_in[1];     // [2,E]
    const int*   batch    = (const int*)d_in[2];     // [N]
    const float* W_embed  = (const float*)d_in[3];   // [2,128,64,8]
    const float* W_mp     = (const float*)d_in[4];   // [3,2,128,128,8]
    const float* W_read   = (const float*)d_in[5];   // [2,32,128,8]
    float* out = (float*)d_out;                      // [64,32]

    float *h0, *h1, *hf, *dinv, *wte, *wtm, *wtr, *sums, *cnts;
    int *deg, *off, *cur, *srcv;
    cudaGetSymbolAddress((void**)&h0,   g_h0);
    cudaGetSymbolAddress((void**)&h1,   g_h1);
    cudaGetSymbolAddress((void**)&hf,   g_hf);
    cudaGetSymbolAddress((void**)&dinv, g_dinv);
    cudaGetSymbolAddress((void**)&deg,  g_deg);
    cudaGetSymbolAddress((void**)&off,  g_off);
    cudaGetSymbolAddress((void**)&cur,  g_cur);
    cudaGetSymbolAddress((void**)&srcv, g_srcv);
    cudaGetSymbolAddress((void**)&wte,  g_wte);
    cudaGetSymbolAddress((void**)&wtm,  g_wtm);
    cudaGetSymbolAddress((void**)&wtr,  g_wtr);
    cudaGetSymbolAddress((void**)&sums, g_sums);
    cudaGetSymbolAddress((void**)&cnts, g_cnts);

    const int* erow = edges;
    const int* ecol = edges + EE;

    // degrees / dinv / CSR by destination (self loops included)
    zero_i32<<<(NN + 255) / 256, 256>>>(deg, NN);
    count_deg<<<(EE + 255) / 256, 256>>>(ecol, deg);
    compute_dinv<<<(NN + 255) / 256, 256>>>(deg, dinv);
    scan_offsets<<<1, 1024>>>(deg, off, cur);
    fill_csr<<<(EE + NN + 255) / 256, 256>>>(erow, ecol, cur, srcv);

    // weight transposes
    transpose_w<<<(64 * 16 * 128 + 255) / 256, 256>>>(W_embed, wte, 64, 128);
    for (int l = 0; l < 3; l++)
        transpose_w<<<(128 * 16 * 128 + 255) / 256, 256>>>(
            W_mp + (size_t)l * 2 * 128 * 128 * 8, wtm + (size_t)l * 128 * 16 * 128, 128, 128);
    transpose_w<<<(128 * 16 * 32 + 255) / 256, 256>>>(W_read, wtr, 128, 32);

    const int gemm_blocks = (NN + 63) / 64;
    const int agg_blocks  = (NN * 32 + 255) / 256;

    // embed: h0 = kan(features)
    kan_gemm<<<gemm_blocks, 256>>>(features, 64, NN, wte, nullptr, nullptr, h0);

    // mp layer 0: hf = dinv .* kan(h0);  h1 = scatter(hf)   (true h1 = dinv .* g_h1, deferred)
    kan_gemm<<<gemm_blocks, 256>>>(h0, 128, NN, wtm, nullptr, dinv, hf);
    aggregate<<<agg_blocks, 256>>>(hf, off, srcv, h1);

    // mp layer 1
    kan_gemm<<<gemm_blocks, 256>>>(h1, 128, NN, wtm + (size_t)1 * 128 * 16 * 128, dinv, dinv, hf);
    aggregate<<<agg_blocks, 256>>>(hf, off, srcv, h0);

    // mp layer 2
    kan_gemm<<<gemm_blocks, 256>>>(h0, 128, NN, wtm + (size_t)2 * 128 * 16 * 128, dinv, dinv, hf);
    aggregate<<<agg_blocks, 256>>>(hf, off, srcv, h1);

    // pooling (applies deferred dinv) + readout
    zero_f32<<<(GG * HIDD + 255) / 256, 256>>>(sums, GG * HIDD);
    zero_f32<<<1, 64>>>(cnts, GG);
    pool_kernel<<<250, 256>>>(h1, batch, dinv, sums, cnts);
    readout_kernel<<<GG, 128>>>(sums, cnts, wtr, out);
}

// round 3
// speedup vs baseline: 3.3787x; 3.3787x over previous
#include <cuda_runtime.h>
#include <cuda_bf16.h>
#include <math.h>
#include <stdint.h>

// ---------------- problem constants ----------------
#define NN   50000
#define EE   1600000
#define GG   64

// ---------------- device scratch (no allocation allowed) ----------------
__device__ float g_h0[(size_t)NN * 128];
__device__ float g_h1[(size_t)NN * 128];
__device__ float g_hf[(size_t)NN * 128];
__device__ float g_dinv[NN];
__device__ int   g_deg[NN];
__device__ int   g_off[NN + 1];
__device__ int   g_cur[NN];
__device__ int   g_srcv[EE + NN];
__device__ int   g_bsum[256];
__device__ int   g_boff[256];
__device__ __nv_bfloat16 g_bhe[128 * 1024];      // embed B hi  [n][k]
__device__ __nv_bfloat16 g_ble[128 * 1024];      // embed B lo
__device__ __nv_bfloat16 g_bhm[3 * 128 * 2048];  // mp B hi x3
__device__ __nv_bfloat16 g_blm[3 * 128 * 2048];  // mp B lo x3
__device__ float g_wtr[2048 * 32];               // readout [k][o] fp32
__device__ float g_sums[GG * 128];
__device__ float g_cnts[GG];

// ---------------- helpers ----------------
__device__ __forceinline__ uint32_t smem_to_u32(const void* p) {
    uint32_t a;
    asm("{ .reg .u64 t; cvta.to.shared.u64 t, %1; cvt.u32.u64 %0, t; }" : "=r"(a) : "l"(p));
    return a;
}
#define SWZ(x) ((x) ^ (((x) >> 3) & 0x70))

#define LDSM4(R, addr)                                                           \
    asm volatile("ldmatrix.sync.aligned.m8n8.x4.shared.b16 {%0,%1,%2,%3}, [%4];" \
                 : "=r"((R)[0]), "=r"((R)[1]), "=r"((R)[2]), "=r"((R)[3])        \
                 : "r"(addr))
#define LDSM2(R, addr)                                                           \
    asm volatile("ldmatrix.sync.aligned.m8n8.x2.shared.b16 {%0,%1}, [%2];"       \
                 : "=r"((R)[0]), "=r"((R)[1]) : "r"(addr))
#define MMA16816(D, A, B)                                                        \
    asm volatile("mma.sync.aligned.m16n8k16.row.col.f32.bf16.bf16.f32 "          \
                 "{%0,%1,%2,%3}, {%4,%5,%6,%7}, {%8,%9}, {%0,%1,%2,%3};"         \
                 : "+f"((D)[0]), "+f"((D)[1]), "+f"((D)[2]), "+f"((D)[3])        \
                 : "r"((A)[0]), "r"((A)[1]), "r"((A)[2]), "r"((A)[3]),           \
                   "r"((B)[0]), "r"((B)[1]))

// ---------------- small utility kernels ----------------
__global__ void zero_i32(int* __restrict__ p, int n) {
    int i = blockIdx.x * blockDim.x + threadIdx.x;
    if (i < n) p[i] = 0;
}
__global__ void zero_f32(float* __restrict__ p, int n) {
    int i = blockIdx.x * blockDim.x + threadIdx.x;
    if (i < n) p[i] = 0.0f;
}
__global__ void count_deg(const int* __restrict__ ecol, int* __restrict__ deg) {
    int e = blockIdx.x * blockDim.x + threadIdx.x;
    if (e < EE) atomicAdd(&deg[ecol[e]], 1);
}
__global__ void compute_dinv(const int* __restrict__ deg, float* __restrict__ dinv) {
    int i = blockIdx.x * blockDim.x + threadIdx.x;
    if (i < NN) dinv[i] = rsqrtf((float)(deg[i] + 1));
}

// ---- parallel exclusive scan of (deg+1): 3 kernels ----
__global__ void deg_bsum(const int* __restrict__ deg, int* __restrict__ bsum) {
    __shared__ int sh[256];
    int t = threadIdx.x;
    int i = blockIdx.x * 256 + t;
    sh[t] = (i < NN) ? deg[i] + 1 : 0;
    __syncthreads();
    for (int d = 128; d > 0; d >>= 1) {
        if (t < d) sh[t] += sh[t + d];
        __syncthreads();
    }
    if (t == 0) bsum[blockIdx.x] = sh[0];
}
__global__ void scan_bsum(const int* __restrict__ bsum, int* __restrict__ boff,
                          int nb, int* __restrict__ off) {
    __shared__ int sh[256];
    int t = threadIdx.x;
    int v = (t < nb) ? bsum[t] : 0;
    sh[t] = v;
    __syncthreads();
    for (int d = 1; d < 256; d <<= 1) {
        int u = (t >= d) ? sh[t - d] : 0;
        __syncthreads();
        sh[t] += u;
        __syncthreads();
    }
    if (t < nb) boff[t] = sh[t] - v;
    if (t == 0) off[NN] = EE + NN;
}
__global__ void scan_write(const int* __restrict__ deg, const int* __restrict__ boff,
                           int* __restrict__ off, int* __restrict__ cur) {
    __shared__ int sh[256];
    int t = threadIdx.x;
    int i = blockIdx.x * 256 + t;
    int v = (i < NN) ? deg[i] + 1 : 0;
    sh[t] = v;
    __syncthreads();
    for (int d = 1; d < 256; d <<= 1) {
        int u = (t >= d) ? sh[t - d] : 0;
        __syncthreads();
        sh[t] += u;
        __syncthreads();
    }
    if (i < NN) {
        int o = boff[blockIdx.x] + sh[t] - v;
        off[i] = o;
        cur[i] = o;
    }
}

__global__ void fill_csr(const int* __restrict__ erow, const int* __restrict__ ecol,
                         int* __restrict__ cur, int* __restrict__ srcv) {
    int e = blockIdx.x * blockDim.x + threadIdx.x;
    if (e >= EE + NN) return;
    int r, c;
    if (e < EE) { r = erow[e]; c = ecol[e]; }
    else        { r = c = e - EE; }
    int p = atomicAdd(&cur[c], 1);
    srcv[p] = r;
}

// W[2][out=128][in][8] -> B[n][k] bf16 hi/lo, k = i*16 + t*8 + h
__global__ void make_b(const float* __restrict__ W, __nv_bfloat16* __restrict__ bhi,
                       __nv_bfloat16* __restrict__ blo, int in_dim) {
    int idx = blockIdx.x * blockDim.x + threadIdx.x;
    int K = in_dim * 16;
    if (idx >= 128 * K) return;
    int n = idx / K;
    int k = idx % K;
    int h = k & 7, t = (k >> 3) & 1, i = k >> 4;
    float w = W[(((size_t)t * 128 + n) * in_dim + i) * 8 + h];
    __nv_bfloat16 hi = __float2bfloat16(w);
    __nv_bfloat16 lo = __float2bfloat16(w - __bfloat162float(hi));
    bhi[idx] = hi;
    blo[idx] = lo;
}

// readout weights W[2][32][128][8] -> Wt[k][o] fp32
__global__ void transpose_wr(const float* __restrict__ W, float* __restrict__ Wt) {
    int idx = blockIdx.x * blockDim.x + threadIdx.x;
    if (idx >= 2048 * 32) return;
    int o = idx % 32;
    int k = idx / 32;
    int h = k & 7, t = (k >> 3) & 1, i = k >> 4;
    Wt[idx] = W[(((size_t)t * 32 + o) * 128 + i) * 8 + h];
}

// ---------------- bf16 hi/lo packing ----------------
__device__ __forceinline__ void cvt8(const float* f, uint4& hi, uint4& lo) {
    uint32_t h[4], l[4];
#pragma unroll
    for (int j = 0; j < 4; ++j) {
        float a = f[2 * j], b = f[2 * j + 1];
        __nv_bfloat16 ah = __float2bfloat16(a), bh = __float2bfloat16(b);
        float ar = a - __bfloat162float(ah);
        float br = b - __bfloat162float(bh);
        __nv_bfloat162 hp; hp.x = ah; hp.y = bh;
        __nv_bfloat162 lp = __floats2bfloat162_rn(ar, br);
        h[j] = *reinterpret_cast<uint32_t*>(&hp);
        l[j] = *reinterpret_cast<uint32_t*>(&lp);
    }
    hi = make_uint4(h[0], h[1], h[2], h[3]);
    lo = make_uint4(l[0], l[1], l[2], l[3]);
}

// ---------------- HMMA KAN GEMM ----------------
// out[row][n] = sum_k phi(in[row])[k] * B[n][k];  block tile 128x128, K = in_dim*16.
// 3-term bf16 hi/lo split (AhBh + AlBh + AhBl), fp32 accumulators.
__global__ __launch_bounds__(256, 2)
void kan_hmma(const float* __restrict__ in, int in_dim,
              const __nv_bfloat16* __restrict__ bhi, const __nv_bfloat16* __restrict__ blo,
              const float* __restrict__ in_scale, const float* __restrict__ out_scale,
              float* __restrict__ out) {
    extern __shared__ char smem[];
    const uint32_t smem_base = smem_to_u32(smem);
    const int A_HI = 0, A_LO = 16384, B_HI = 32768, B_LO = 49152;

    const int tid  = threadIdx.x;
    const int wid  = tid >> 5, lane = tid & 31;
    const int row0 = blockIdx.x * 128;

    // warp tile: m-offset (wid>>2)*64, n-offset (wid&3)*32
    const int m0 = (wid >> 2) * 64;
    const int n0 = (wid & 3) * 32;

    float acc[4][4][4];
#pragma unroll
    for (int a = 0; a < 4; a++)
#pragma unroll
        for (int b = 0; b < 4; b++)
#pragma unroll
            for (int c2 = 0; c2 < 4; c2++) acc[a][b][c2] = 0.0f;

    const int arow = tid & 127;
    const int ail  = tid >> 7;       // features ail, ail+2 of each 4-chunk
    const int grow = row0 + arow;
    const bool rv  = grow < NN;
    const float isc = (rv && in_scale) ? in_scale[grow] : 1.0f;
    const int Kb = in_dim * 32;      // B row stride in bytes
    const int nchunks = in_dim / 4;  // 64 k per chunk

    // precomputed fragment addresses (within-tile offsets)
    const uint32_t a_off = SWZ((uint32_t)((lane & 15) * 128 + (lane >> 4) * 16));
    const uint32_t b_off = SWZ((uint32_t)(((lane & 15) & 7) * 128 + (((lane & 15) >> 3) & 1) * 16));

    for (int c = 0; c < nchunks; ++c) {
        __syncthreads();
        // --- A tile: phi expansion, bf16 hi/lo, SW128 swizzled ---
#pragma unroll
        for (int q = 0; q < 2; ++q) {
            const int il = ail + 2 * q;
            float x = rv ? in[(size_t)grow * in_dim + c * 4 + il] * isc : 0.0f;
            float s1, c1;
            sincosf(x, &s1, &c1);
            float cv[8], sv[8];
            cv[0] = c1; sv[0] = s1;
            const float t2 = 2.0f * c1;
            float cp = 1.0f, sp = 0.0f;
#pragma unroll
            for (int h = 1; h < 8; ++h) {
                float cn = t2 * cv[h - 1] - cp;
                float sn = t2 * sv[h - 1] - sp;
                cp = cv[h - 1]; sp = sv[h - 1];
                cv[h] = cn; sv[h] = sn;
            }
            uint4 chi, clo, shi, slo;
            cvt8(cv, chi, clo);
            cvt8(sv, shi, slo);
            const uint32_t bo = (uint32_t)(arow * 128 + il * 32);
            *reinterpret_cast<uint4*>(smem + A_HI + SWZ(bo))      = chi;
            *reinterpret_cast<uint4*>(smem + A_LO + SWZ(bo))      = clo;
            *reinterpret_cast<uint4*>(smem + A_HI + SWZ(bo + 16)) = shi;
            *reinterpret_cast<uint4*>(smem + A_LO + SWZ(bo + 16)) = slo;
        }
        // --- B tile: 128 n-rows x 64 bf16 ---
        {
            const char* ph = (const char*)bhi + c * 128;
            const char* pl = (const char*)blo + c * 128;
#pragma unroll
            for (int r = 0; r < 4; ++r) {
                int idx = tid + 256 * r;
                int n = idx >> 3, seg = idx & 7;
                uint32_t so = SWZ((uint32_t)(n * 128 + seg * 16));
                *reinterpret_cast<uint4*>(smem + B_HI + so) =
                    *reinterpret_cast<const uint4*>(ph + (size_t)n * Kb + seg * 16);
                *reinterpret_cast<uint4*>(smem + B_LO + so) =
                    *reinterpret_cast<const uint4*>(pl + (size_t)n * Kb + seg * 16);
            }
        }
        __syncthreads();
        // --- compute: 4 k16 steps ---
#pragma unroll
        for (int kk = 0; kk < 4; ++kk) {
            const uint32_t kb = kk * 32;
            uint32_t bh[4][2], bl[4][2];
#pragma unroll
            for (int nt = 0; nt < 4; ++nt) {
                uint32_t off = (uint32_t)((n0 + nt * 8) * 128 + kb);
                // b_off already contains lane-relative swizzled part; recompute exact:
                uint32_t addr = smem_base + SWZ((uint32_t)((n0 + nt * 8 + ((lane & 15) & 7)) * 128 + kb + (((lane & 15) >> 3) & 1) * 16));
                LDSM2(bh[nt], addr + B_HI);
                LDSM2(bl[nt], addr + B_LO);
                (void)off;
            }
#pragma unroll
            for (int mt = 0; mt < 4; ++mt) {
                uint32_t addr = smem_base + SWZ((uint32_t)((m0 + mt * 16 + (lane & 15)) * 128 + kb + (lane >> 4) * 16));
                uint32_t ah[4], al[4];
                LDSM4(ah, addr + A_HI);
                LDSM4(al, addr + A_LO);
#pragma unroll
                for (int nt = 0; nt < 4; ++nt) {
                    MMA16816(acc[mt][nt], ah, bh[nt]);
                    MMA16816(acc[mt][nt], al, bh[nt]);
                    MMA16816(acc[mt][nt], ah, bl[nt]);
                }
            }
        }
    }
    (void)a_off; (void)b_off;

    // --- epilogue ---
    const int g4 = lane >> 2, t4 = lane & 3;
#pragma unroll
    for (int mt = 0; mt < 4; ++mt) {
        int r0 = row0 + m0 + mt * 16 + g4;
        int r1 = r0 + 8;
        float sc0 = 1.0f, sc1 = 1.0f;
        bool v0 = r0 < NN, v1 = r1 < NN;
        if (out_scale) {
            if (v0) sc0 = out_scale[r0];
            if (v1) sc1 = out_scale[r1];
        }
#pragma unroll
        for (int nt = 0; nt < 4; ++nt) {
            int col = n0 + nt * 8 + t4 * 2;
            if (v0) {
                float2* p = reinterpret_cast<float2*>(out + (size_t)r0 * 128 + col);
                *p = make_float2(acc[mt][nt][0] * sc0, acc[mt][nt][1] * sc0);
            }
            if (v1) {
                float2* p = reinterpret_cast<float2*>(out + (size_t)r1 * 128 + col);
                *p = make_float2(acc[mt][nt][2] * sc1, acc[mt][nt][3] * sc1);
            }
        }
    }
}

// ---------------- CSR aggregation ----------------
__global__ void aggregate(const float* __restrict__ hf,
                          const int* __restrict__ off, const int* __restrict__ srcv,
                          float* __restrict__ out) {
    int warp = (blockIdx.x * blockDim.x + threadIdx.x) >> 5;
    int lane = threadIdx.x & 31;
    if (warp >= NN) return;
    int e  = off[warp];
    int e1 = off[warp + 1];
    float4 a0 = make_float4(0.f, 0.f, 0.f, 0.f);
    float4 a1 = make_float4(0.f, 0.f, 0.f, 0.f);
    for (; e + 1 < e1; e += 2) {
        int r0 = __ldg(&srcv[e]);
        int r1 = __ldg(&srcv[e + 1]);
        float4 v0 = *reinterpret_cast<const float4*>(hf + (size_t)r0 * 128 + lane * 4);
        float4 v1 = *reinterpret_cast<const float4*>(hf + (size_t)r1 * 128 + lane * 4);
        a0.x += v0.x; a0.y += v0.y; a0.z += v0.z; a0.w += v0.w;
        a1.x += v1.x; a1.y += v1.y; a1.z += v1.z; a1.w += v1.w;
    }
    if (e < e1) {
        int r0 = __ldg(&srcv[e]);
        float4 v0 = *reinterpret_cast<const float4*>(hf + (size_t)r0 * 128 + lane * 4);
        a0.x += v0.x; a0.y += v0.y; a0.z += v0.z; a0.w += v0.w;
    }
    a0.x += a1.x; a0.y += a1.y; a0.z += a1.z; a0.w += a1.w;
    *reinterpret_cast<float4*>(out + (size_t)warp * 128 + lane * 4) = a0;
}

// ---------------- pooling ----------------
__global__ void pool_kernel(const float* __restrict__ h, const int* __restrict__ batch,
                            const float* __restrict__ dinv,
                            float* __restrict__ sums, float* __restrict__ cnts) {
    const int PER = 25;
    int warp = (blockIdx.x * blockDim.x + threadIdx.x) >> 5;
    int lane = threadIdx.x & 31;
    int n0 = warp * PER;
    if (n0 >= NN) return;
    int n1 = n0 + PER;
    if (n1 > NN) n1 = NN;
    float4 acc = make_float4(0.f, 0.f, 0.f, 0.f);
    float cnt = 0.f;
    int cg = batch[n0];
    for (int n = n0; n < n1; n++) {
        int g = batch[n];
        if (g != cg) {
            float* p = sums + (size_t)cg * 128 + lane * 4;
            atomicAdd(p + 0, acc.x); atomicAdd(p + 1, acc.y);
            atomicAdd(p + 2, acc.z); atomicAdd(p + 3, acc.w);
            if (lane == 0) atomicAdd(&cnts[cg], cnt);
            acc = make_float4(0.f, 0.f, 0.f, 0.f);
            cnt = 0.f; cg = g;
        }
        float w = dinv[n];
        float4 v = *reinterpret_cast<const float4*>(h + (size_t)n * 128 + lane * 4);
        acc.x += w * v.x; acc.y += w * v.y; acc.z += w * v.z; acc.w += w * v.w;
        cnt += 1.f;
    }
    float* p = sums + (size_t)cg * 128 + lane * 4;
    atomicAdd(p + 0, acc.x); atomicAdd(p + 1, acc.y);
    atomicAdd(p + 2, acc.z); atomicAdd(p + 3, acc.w);
    if (lane == 0) atomicAdd(&cnts[cg], cnt);
}

// ---------------- readout ----------------
__global__ void readout_kernel(const float* __restrict__ sums, const float* __restrict__ cnts,
                               const float* __restrict__ Wt,
                               float* __restrict__ out) {
    __shared__ float phi[2048];
    __shared__ float red[4][32];
    const int g = blockIdx.x;
    const int tid = threadIdx.x;     // 128 threads
    float cnt = fmaxf(cnts[g], 1.0f);
    float x = sums[(size_t)g * 128 + tid] / cnt;
    float s1, c1;
    sincosf(x, &s1, &c1);
    const float twoc = 2.0f * c1;
    float cp = 1.0f, sp = 0.0f, cc = c1, ss = s1;
#pragma unroll
    for (int h = 0; h < 8; h++) {
        phi[tid * 16 + h]     = cc;
        phi[tid * 16 + 8 + h] = ss;
        float cn = twoc * cc - cp;
        float sn = twoc * ss - sp;
        cp = cc; sp = ss; cc = cn; ss = sn;
    }
    __syncthreads();
    const int o = tid & 31;
    const int part = tid >> 5;
    float acc = 0.f;
    int k0 = part * 512;
#pragma unroll 8
    for (int k = k0; k < k0 + 512; k++) acc += phi[k] * Wt[k * 32 + o];
    red[part][o] = acc;
    __syncthreads();
    if (tid < 32)
        out[(size_t)g * 32 + tid] = red[0][tid] + red[1][tid] + red[2][tid] + red[3][tid];
}

// ---------------- launch ----------------
extern "C" void kernel_launch(void* const* d_in, const int* in_sizes, int n_in,
                              void* d_out, int out_size) {
    const float* features = (const float*)d_in[0];   // [N,64]
    const int*   edges    = (const int*)d_in[1];     // [2,E]
    const int*   batch    = (const int*)d_in[2];     // [N]
    const float* W_embed  = (const float*)d_in[3];   // [2,128,64,8]
    const float* W_mp     = (const float*)d_in[4];   // [3,2,128,128,8]
    const float* W_read   = (const float*)d_in[5];   // [2,32,128,8]
    float* out = (float*)d_out;                      // [64,32]

    float *h0, *h1, *hf, *dinv, *wtr, *sums, *cnts;
    int *deg, *off, *cur, *srcv, *bsum, *boff;
    __nv_bfloat16 *bhe, *ble, *bhm, *blm;
    cudaGetSymbolAddress((void**)&h0,   g_h0);
    cudaGetSymbolAddress((void**)&h1,   g_h1);
    cudaGetSymbolAddress((void**)&hf,   g_hf);
    cudaGetSymbolAddress((void**)&dinv, g_dinv);
    cudaGetSymbolAddress((void**)&deg,  g_deg);
    cudaGetSymbolAddress((void**)&off,  g_off);
    cudaGetSymbolAddress((void**)&cur,  g_cur);
    cudaGetSymbolAddress((void**)&srcv, g_srcv);
    cudaGetSymbolAddress((void**)&bsum, g_bsum);
    cudaGetSymbolAddress((void**)&boff, g_boff);
    cudaGetSymbolAddress((void**)&bhe,  g_bhe);
    cudaGetSymbolAddress((void**)&ble,  g_ble);
    cudaGetSymbolAddress((void**)&bhm,  g_bhm);
    cudaGetSymbolAddress((void**)&blm,  g_blm);
    cudaGetSymbolAddress((void**)&wtr,  g_wtr);
    cudaGetSymbolAddress((void**)&sums, g_sums);
    cudaGetSymbolAddress((void**)&cnts, g_cnts);

    const int* erow = edges;
    const int* ecol = edges + EE;

    cudaFuncSetAttribute(kan_hmma, cudaFuncAttributeMaxDynamicSharedMemorySize, 65536);

    // CSR build (destination-indexed, self loops appended)
    zero_i32<<<(NN + 255) / 256, 256>>>(deg, NN);
    count_deg<<<(EE + 255) / 256, 256>>>(ecol, deg);
    compute_dinv<<<(NN + 255) / 256, 256>>>(deg, dinv);
    const int nb = (NN + 255) / 256;  // 196
    deg_bsum<<<nb, 256>>>(deg, bsum);
    scan_bsum<<<1, 256>>>(bsum, boff, nb, off);
    scan_write<<<nb, 256>>>(deg, boff, off, cur);
    fill_csr<<<(EE + NN + 255) / 256, 256>>>(erow, ecol, cur, srcv);

    // weight prep: bf16 hi/lo [n][k]
    make_b<<<(128 * 1024 + 255) / 256, 256>>>(W_embed, bhe, ble, 64);
    for (int l = 0; l < 3; l++)
        make_b<<<(128 * 2048 + 255) / 256, 256>>>(
            W_mp + (size_t)l * 2 * 128 * 128 * 8,
            bhm + (size_t)l * 128 * 2048, blm + (size_t)l * 128 * 2048, 128);
    transpose_wr<<<(2048 * 32 + 255) / 256, 256>>>(W_read, wtr);

    const int gblocks = (NN + 127) / 128;   // 391
    const int agg_blocks = (NN * 32 + 255) / 256;
    const size_t SMB = 65536;

    // embed
    kan_hmma<<<gblocks, 256, SMB>>>(features, 64, bhe, ble, nullptr, nullptr, h0);
    // mp 0
    kan_hmma<<<gblocks, 256, SMB>>>(h0, 128, bhm, blm, nullptr, dinv, hf);
    aggregate<<<agg_blocks, 256>>>(hf, off, srcv, h1);
    // mp 1
    kan_hmma<<<gblocks, 256, SMB>>>(h1, 128, bhm + 128 * 2048, blm + 128 * 2048, dinv, dinv, hf);
    aggregate<<<agg_blocks, 256>>>(hf, off, srcv, h0);
    // mp 2
    kan_hmma<<<gblocks, 256, SMB>>>(h0, 128, bhm + 2 * 128 * 2048, blm + 2 * 128 * 2048, dinv, dinv, hf);
    aggregate<<<agg_blocks, 256>>>(hf, off, srcv, h1);

    // pool + readout
    zero_f32<<<(GG * 128 + 255) / 256, 256>>>(sums, GG * 128);
    zero_f32<<<1, 64>>>(cnts, GG);
    pool_kernel<<<250, 256>>>(h1, batch, dinv, sums, cnts);
    readout_kernel<<<GG, 128>>>(sums, cnts, wtr, out);
}